// round 5
// baseline (speedup 1.0000x reference)
#include <cuda_runtime.h>
#include <cuda_bf16.h>
#include <cstdint>

// Problem constants
#define BB   32      // batch
#define DD   4096    // model dim
#define HH   32      // q heads
#define HKV  8       // kv heads
#define GG   4       // q heads per kv head
#define DH   128     // head dim
#define TT   4096    // cache length
#define EQKV 6144    // 4096 + 1024 + 1024
#define SPLITS 32    // K-splits for projections
#define DSPL 128     // d per split (4096/32)

// attention split config
#define NSPLIT 8     // token splits per (b,kvh)
#define TSPLIT 512   // TT / NSPLIT
#define CH     32    // tokens per chunk

// ---------------- scratch (device globals; no runtime allocation) ----------------
__device__ float g_xq[BB * HH * DH];
__device__ float g_xk[BB * HKV * DH];
__device__ float g_v [BB * HKV * DH];
__device__ float g_q [BB * HH * DH];
__device__ float g_k [BB * HKV * DH];
__device__ float g_attn[BB * HH * DH];
__device__ float g_P1[SPLITS * BB * EQKV];               // qkv partials
__device__ float g_P2[SPLITS * BB * DD];                 // wo partials
__device__ float g_pacc[BB * HKV * NSPLIT * GG * DH];    // flash partial acc
__device__ float g_pml [BB * HKV * NSPLIT * GG * 2];     // flash partial (m,l)

// ---------------- packed fp32x2 helpers (FFMA2 path, sm_100+) ----------------
__device__ __forceinline__ unsigned long long pk2(float lo, float hi) {
    unsigned long long r;
    asm("mov.b64 %0, {%1,%2};" : "=l"(r) : "f"(lo), "f"(hi));
    return r;
}
__device__ __forceinline__ void upk2(unsigned long long v, float& lo, float& hi) {
    asm("mov.b64 {%0,%1}, %2;" : "=f"(lo), "=f"(hi) : "l"(v));
}
__device__ __forceinline__ void fma2(unsigned long long& d, unsigned long long a, unsigned long long b) {
    asm("fma.rn.f32x2 %0, %1, %2, %0;" : "+l"(d) : "l"(a), "l"(b));
}

// ---------------- projection GEMV body ----------------
// out[b][e] = sum_d x[b][d] * w[d][e], M=32 rows, split over d.
// 256 threads; thread owns 2 consecutive columns; 8-deep weight prefetch (MLP 8).
__device__ __forceinline__ void proj_body(
    const float* __restrict__ x, const float* __restrict__ w,
    int Ew, int le0, int gcol0, int d0,
    float* __restrict__ part, int partE)
{
    __shared__ float xs[DSPL * BB];   // 16 KB, [d_local][b]
    const int tid = threadIdx.x;

    #pragma unroll
    for (int k = 0; k < 16; k++) {
        int idx = tid + k * 256;
        int dl = idx >> 5, bb = idx & 31;
        xs[dl * 32 + bb] = x[bb * DD + d0 + dl];
    }
    __syncthreads();

    const unsigned long long* xs2 = (const unsigned long long*)xs; // [d_local][16 pairs]

    unsigned long long acc[16][2];
    #pragma unroll
    for (int jp = 0; jp < 16; jp++) { acc[jp][0] = 0ull; acc[jp][1] = 0ull; }

    const float* wp = w + (size_t)d0 * Ew + le0 + tid * 2;

    for (int blk = 0; blk < DSPL / 8; blk++) {
        float2 wreg[8];
        #pragma unroll
        for (int u = 0; u < 8; u++)
            wreg[u] = *(const float2*)(wp + (size_t)u * Ew);
        #pragma unroll
        for (int u = 0; u < 8; u++) {
            int dl = blk * 8 + u;
            unsigned long long uA = pk2(wreg[u].x, wreg[u].x);
            unsigned long long uB = pk2(wreg[u].y, wreg[u].y);
            const unsigned long long* xr = xs2 + dl * 16;
            #pragma unroll
            for (int jp = 0; jp < 16; jp++) {
                unsigned long long xv = xr[jp];
                fma2(acc[jp][0], uA, xv);
                fma2(acc[jp][1], uB, xv);
            }
        }
        wp += (size_t)8 * Ew;
    }

    const int split = blockIdx.y;
    float* pb = part + (size_t)split * BB * partE + gcol0 + tid * 2;
    #pragma unroll
    for (int jp = 0; jp < 16; jp++) {
        float lo0, hi0, lo1, hi1;
        upk2(acc[jp][0], lo0, hi0);
        upk2(acc[jp][1], lo1, hi1);
        *(float2*)(pb + (size_t)(2 * jp) * partE)     = make_float2(lo0, lo1);
        *(float2*)(pb + (size_t)(2 * jp + 1) * partE) = make_float2(hi0, hi1);
    }
}

__global__ void __launch_bounds__(256)
proj_qkv_kernel(const float* __restrict__ x, const float* __restrict__ wq,
                const float* __restrict__ wk, const float* __restrict__ wv)
{
    int e0 = blockIdx.x * 512;
    const float* w; int Ew, le0;
    if (e0 < 4096)      { w = wq; Ew = 4096; le0 = e0; }
    else if (e0 < 5120) { w = wk; Ew = 1024; le0 = e0 - 4096; }
    else                { w = wv; Ew = 1024; le0 = e0 - 5120; }
    proj_body(x, w, Ew, le0, e0, blockIdx.y * DSPL, g_P1, EQKV);
}

__global__ void __launch_bounds__(256)
proj_o_kernel(const float* __restrict__ wo)
{
    int e0 = blockIdx.x * 512;
    proj_body(g_attn, wo, DD, e0, e0, blockIdx.y * DSPL, g_P2, DD);
}

// ---------------- reductions over K-splits ----------------
__global__ void reduce_qkv_kernel()
{
    int idx = blockIdx.x * 256 + threadIdx.x;
    if (idx >= BB * EQKV) return;
    int b = idx / EQKV, col = idx % EQKV;
    float s = 0.f;
    #pragma unroll 8
    for (int sp = 0; sp < SPLITS; sp++)
        s += g_P1[((size_t)sp * BB + b) * EQKV + col];
    if (col < 4096)      g_xq[b * 4096 + col] = s;
    else if (col < 5120) g_xk[b * 1024 + (col - 4096)] = s;
    else                 g_v [b * 1024 + (col - 5120)] = s;
}

__global__ void reduce_o_kernel(float* __restrict__ out)
{
    int idx = blockIdx.x * 256 + threadIdx.x;
    if (idx >= BB * DD) return;
    int b = idx >> 12, col = idx & 4095;
    float s = 0.f;
    #pragma unroll 8
    for (int sp = 0; sp < SPLITS; sp++)
        s += g_P2[((size_t)sp * BB + b) * DD + col];
    out[b * DD + col] = s;
}

// ---------------- RoPE ----------------
__global__ void rotate_kernel(const float* __restrict__ rot, int rot_b_stride)
{
    int hh = blockIdx.x, b = blockIdx.y, tid = threadIdx.x;
    __shared__ float xs[DH];
    const float* src; float* dst;
    if (hh < HH) { src = g_xq + (b * HH + hh) * DH; dst = g_q + (b * HH + hh) * DH; }
    else         { src = g_xk + (b * HKV + (hh - HH)) * DH; dst = g_k + (b * HKV + (hh - HH)) * DH; }
    xs[tid] = src[tid];
    __syncthreads();
    const float* R = rot + (size_t)b * rot_b_stride;
    float a = 0.f;
    #pragma unroll 8
    for (int d = 0; d < DH; d++) a += xs[d] * R[d * DH + tid];
    dst[tid] = a;
}

// ---------------- flash decode: K double-buffered, V single, 4 barriers/chunk ----------------
// SMEM floats:
#define SM_K0   0
#define SM_K1   4096
#define SM_V    8192
#define SM_QS   12288
#define SM_PSC  12800
#define SM_WM   12928
#define SM_SL   12960
#define SM_MRUN 12992
#define SM_LRUN 12996
#define SM_FS   13000
#define SM_MM   13004
#define SM_OUT  13008
#define ATTN_SMEM_FLOATS 13520

__device__ __forceinline__ void issue_tile(
    float* buf, const float* __restrict__ base, const float* __restrict__ fresh,
    int t0c, int sp, int tid)
{
    #pragma unroll
    for (int it = 0; it < 4; it++) {
        int fl = it * 256 + tid;
        int j = fl >> 5, f = fl & 31;
        int t = t0c + j;
        const float* src = (t == sp) ? (fresh + f * 4) : (base + (size_t)t * DH + f * 4);
        uint32_t dst = (uint32_t)__cvta_generic_to_shared(buf + j * 128 + ((f ^ (j & 7)) << 2));
        asm volatile("cp.async.cg.shared.global [%0], [%1], 16;" :: "r"(dst), "l"(src));
    }
}

__global__ void __launch_bounds__(256, 4)
attn_kernel(const float* __restrict__ kc, const float* __restrict__ vc,
            const int* __restrict__ sp_ptr)
{
    extern __shared__ float smem[];
    const int split = blockIdx.x, kvh = blockIdx.y, b = blockIdx.z;
    const int sp = *sp_ptr;
    const int t0s = split * TSPLIT;
    if (t0s > sp) return;
    const int active = min(TSPLIT, sp + 1 - t0s);
    const int nch = (active + CH - 1) / CH;

    const int tid = threadIdx.x;
    const int bkv = b * HKV + kvh;

    const float* kbase = kc + (size_t)bkv * TT * DH;
    const float* vbase = vc + (size_t)bkv * TT * DH;
    const float* gk = g_k + (size_t)bkv * DH;
    const float* gv = g_v + (size_t)bkv * DH;

    // prologue: stage q (scaled, plain [g][d]), init state, issue K0
    if (tid < 128) {
        int g = tid >> 5, c = tid & 31;
        const float sc = 0.08838834764831845f;   // 1/sqrt(128)
        float4 qv = *(const float4*)(g_q + (size_t)(b * HH + kvh * GG + g) * DH + c * 4);
        ((float4*)(smem + SM_QS))[g * 32 + c] =
            make_float4(qv.x * sc, qv.y * sc, qv.z * sc, qv.w * sc);
    }
    if (tid < 4) { smem[SM_MRUN + tid] = -1e30f; smem[SM_LRUN + tid] = 0.f; }

    issue_tile(smem + SM_K0, kbase, gk, t0s, sp, tid);
    asm volatile("cp.async.commit_group;");

    // value-phase persistent accumulators: thread = (d, token-half)
    const int d = tid & 127, vhalf = tid >> 7;
    float acc0 = 0.f, acc1 = 0.f, acc2 = 0.f, acc3 = 0.f;

    // score-phase mapping: thread = (token j, 16-dim slice c)
    const int sj = tid >> 3, c8 = tid & 7;
    const int wid = tid >> 5, lane = tid & 31;

    for (int ic = 0; ic < nch; ic++) {
        __syncthreads();                                   // B1: V buf free, PSC free

        // issue V(ic) (single buffer, covered by scores+softmax)
        issue_tile(smem + SM_V, vbase, gv, t0s + ic * CH, sp, tid);
        asm volatile("cp.async.commit_group;");

        asm volatile("cp.async.wait_group 1;");            // K(ic) ready (V pending ok)
        __syncthreads();                                   // B2: all see K tile

        float* kb = smem + ((ic & 1) ? SM_K1 : SM_K0);

        // ---- scores: K read once, q broadcast ----
        float s0 = 0.f, s1 = 0.f, s2 = 0.f, s3 = 0.f;
        {
            const float4* kr = (const float4*)kb + sj * 32;
            const float4* qb = (const float4*)(smem + SM_QS);
            #pragma unroll
            for (int u = 0; u < 4; u++) {
                int f = c8 * 4 + u;
                float4 k4 = kr[f ^ (sj & 7)];
                float4 q0 = qb[0 * 32 + f];
                float4 q1 = qb[1 * 32 + f];
                float4 q2 = qb[2 * 32 + f];
                float4 q3 = qb[3 * 32 + f];
                s0 += k4.x*q0.x + k4.y*q0.y + k4.z*q0.z + k4.w*q0.w;
                s1 += k4.x*q1.x + k4.y*q1.y + k4.z*q1.z + k4.w*q1.w;
                s2 += k4.x*q2.x + k4.y*q2.y + k4.z*q2.z + k4.w*q2.w;
                s3 += k4.x*q3.x + k4.y*q3.y + k4.z*q3.z + k4.w*q3.w;
            }
        }
        // issue K(ic+1) while reductions run
        if (ic + 1 < nch)
            issue_tile(smem + (((ic + 1) & 1) ? SM_K1 : SM_K0),
                       kbase, gk, t0s + (ic + 1) * CH, sp, tid);
        asm volatile("cp.async.commit_group;");

        // reduce over 8 c-lanes
        #pragma unroll
        for (int off = 1; off <= 4; off <<= 1) {
            s0 += __shfl_xor_sync(0xffffffffu, s0, off);
            s1 += __shfl_xor_sync(0xffffffffu, s1, off);
            s2 += __shfl_xor_sync(0xffffffffu, s2, off);
            s3 += __shfl_xor_sync(0xffffffffu, s3, off);
        }
        int tj = t0s + ic * CH + sj;
        if (tj > sp) { s0 = s1 = s2 = s3 = -1e30f; }
        if (c8 == 0) ((float4*)(smem + SM_PSC))[sj] = make_float4(s0, s1, s2, s3);
        // warp max over its 4 tokens
        #pragma unroll
        for (int off = 8; off <= 16; off <<= 1) {
            s0 = fmaxf(s0, __shfl_xor_sync(0xffffffffu, s0, off));
            s1 = fmaxf(s1, __shfl_xor_sync(0xffffffffu, s1, off));
            s2 = fmaxf(s2, __shfl_xor_sync(0xffffffffu, s2, off));
            s3 = fmaxf(s3, __shfl_xor_sync(0xffffffffu, s3, off));
        }
        if (lane == 0) {
            smem[SM_WM + wid * 4 + 0] = s0; smem[SM_WM + wid * 4 + 1] = s1;
            smem[SM_WM + wid * 4 + 2] = s2; smem[SM_WM + wid * 4 + 3] = s3;
        }
        __syncthreads();                                   // B3

        if (tid < 4) {
            float bm = smem[SM_WM + tid];
            #pragma unroll
            for (int w = 1; w < 8; w++) bm = fmaxf(bm, smem[SM_WM + w * 4 + tid]);
            float mold = smem[SM_MRUN + tid];
            float M = fmaxf(mold, bm);
            smem[SM_FS + tid] = __expf(mold - M);
            smem[SM_MM + tid] = M;
            smem[SM_MRUN + tid] = M;
        }
        __syncthreads();                                   // B4 (half-barrier role)

        if (tid < 128) {
            int g2 = tid & 3, j2 = tid >> 2;
            float p = __expf(smem[SM_PSC + j2 * 4 + g2] - smem[SM_MM + g2]);
            smem[SM_PSC + j2 * 4 + g2] = p;
            float l = p;
            l += __shfl_xor_sync(0xffffffffu, l, 4);
            l += __shfl_xor_sync(0xffffffffu, l, 8);
            l += __shfl_xor_sync(0xffffffffu, l, 16);
            if ((tid & 31) < 4) smem[SM_SL + (tid >> 5) * 4 + g2] = l;
        }
        asm volatile("cp.async.wait_group 1;");            // V(ic) ready
        __syncthreads();                                   // B5

        if (tid < 4)
            smem[SM_LRUN + tid] = smem[SM_LRUN + tid] * smem[SM_FS + tid]
                + smem[SM_SL + tid] + smem[SM_SL + 4 + tid]
                + smem[SM_SL + 8 + tid] + smem[SM_SL + 12 + tid];

        // ---- value phase ----
        {
            float f0 = smem[SM_FS + 0], f1 = smem[SM_FS + 1];
            float f2 = smem[SM_FS + 2], f3 = smem[SM_FS + 3];
            acc0 *= f0; acc1 *= f1; acc2 *= f2; acc3 *= f3;
            const float* vb = smem + SM_V;
            #pragma unroll 4
            for (int jj = 0; jj < 16; jj++) {
                int jr = vhalf * 16 + jj;
                float4 p4 = *(const float4*)(smem + SM_PSC + jr * 4);
                float v = vb[jr * 128 + ((((d >> 2) ^ (jr & 7)) << 2) | (d & 3))];
                acc0 += p4.x * v; acc1 += p4.y * v; acc2 += p4.z * v; acc3 += p4.w * v;
            }
        }
    }

    // ---- epilogue: merge halves, write partials ----
    __syncthreads();
    if (vhalf == 0) {
        smem[SM_OUT + 0 * 128 + d] = acc0;
        smem[SM_OUT + 1 * 128 + d] = acc1;
        smem[SM_OUT + 2 * 128 + d] = acc2;
        smem[SM_OUT + 3 * 128 + d] = acc3;
    }
    __syncthreads();
    if (vhalf == 1) {
        smem[SM_OUT + 0 * 128 + d] += acc0;
        smem[SM_OUT + 1 * 128 + d] += acc1;
        smem[SM_OUT + 2 * 128 + d] += acc2;
        smem[SM_OUT + 3 * 128 + d] += acc3;
    }
    __syncthreads();

    size_t obase = (((size_t)bkv * NSPLIT + split) * GG) * DH;
    for (int r = tid; r < GG * DH; r += 256)
        g_pacc[obase + r] = smem[SM_OUT + r];
    if (tid < 4) {
        size_t mlb = (((size_t)bkv * NSPLIT + split) * GG + tid) * 2;
        g_pml[mlb] = smem[SM_MRUN + tid];
        g_pml[mlb + 1] = smem[SM_LRUN + tid];
    }
}

// ---------------- combine split-KV partials ----------------
__global__ void combine_kernel(const int* __restrict__ sp_ptr)
{
    const int h = blockIdx.x, b = blockIdx.y, d = threadIdx.x;
    const int sp = *sp_ptr;
    const int nact = sp / TSPLIT + 1;
    const int kvh = h >> 2, g = h & 3;
    const int bkv = b * HKV + kvh;

    float M = -1e30f;
    for (int c = 0; c < nact; c++)
        M = fmaxf(M, g_pml[(((size_t)bkv * NSPLIT + c) * GG + g) * 2]);

    float L = 0.f, acc = 0.f;
    for (int c = 0; c < nact; c++) {
        size_t mlb = (((size_t)bkv * NSPLIT + c) * GG + g) * 2;
        float f = __expf(g_pml[mlb] - M);
        L += g_pml[mlb + 1] * f;
        acc += g_pacc[(((size_t)bkv * NSPLIT + c) * GG + g) * DH + d] * f;
    }
    g_attn[(size_t)(b * HH + h) * DH + d] = acc / L;
}

// ---------------- launcher ----------------
extern "C" void kernel_launch(void* const* d_in, const int* in_sizes, int n_in,
                              void* d_out, int out_size)
{
    const float* x   = (const float*)d_in[0];
    const float* wq  = (const float*)d_in[1];
    const float* wk  = (const float*)d_in[2];
    const float* wv  = (const float*)d_in[3];
    const float* wo  = (const float*)d_in[4];
    const float* rot = (const float*)d_in[5];
    // d_in[6] = attn_mask: not read (semantics derived from start_pos)
    const float* kc  = (const float*)d_in[7];
    const float* vc  = (const float*)d_in[8];
    const int*   sp  = (const int*)d_in[9];
    float* out = (float*)d_out;

    int rot_b_stride = (in_sizes[5] >= BB * DH * DH) ? DH * DH : 0;

    cudaFuncSetAttribute(attn_kernel, cudaFuncAttributeMaxDynamicSharedMemorySize,
                         ATTN_SMEM_FLOATS * 4);

    proj_qkv_kernel<<<dim3(EQKV / 512, SPLITS), 256>>>(x, wq, wk, wv);
    reduce_qkv_kernel<<<(BB * EQKV + 255) / 256, 256>>>();
    rotate_kernel<<<dim3(HH + HKV, BB), DH>>>(rot, rot_b_stride);
    attn_kernel<<<dim3(NSPLIT, HKV, BB), 256, ATTN_SMEM_FLOATS * 4>>>(kc, vc, sp);
    combine_kernel<<<dim3(HH, BB), DH>>>(sp);
    proj_o_kernel<<<dim3(DD / 512, SPLITS), 256>>>(wo);
    reduce_o_kernel<<<(BB * DD + 255) / 256, 256>>>(out);
}

// round 6
// speedup vs baseline: 1.8548x; 1.8548x over previous
#include <cuda_runtime.h>
#include <cuda_bf16.h>
#include <cstdint>

// Problem constants
#define BB   32      // batch
#define DD   4096    // model dim
#define HH   32      // q heads
#define HKV  8       // kv heads
#define GG   4       // q heads per kv head
#define DH   128     // head dim
#define TT   4096    // cache length
#define EQKV 6144    // 4096 + 1024 + 1024
#define SPLITS 32    // K-splits for projections
#define DSPL 128     // d per split (4096/32)
#define XSTR 34      // padded smem stride for x tile (even, conflict-free)

// attention split config
#define TCH    256   // tokens per CTA
#define NSPLIT 16    // TT / TCH

// ---------------- scratch (device globals; no runtime allocation) ----------------
__device__ float g_xq[BB * HH * DH];
__device__ float g_xk[BB * HKV * DH];
__device__ float g_v [BB * HKV * DH];
__device__ float g_q [BB * HH * DH];
__device__ float g_k [BB * HKV * DH];
__device__ float g_attn[BB * HH * DH];
__device__ float g_P1[SPLITS * BB * EQKV];               // qkv partials
__device__ float g_P2[SPLITS * BB * DD];                 // wo partials
__device__ float g_pacc[BB * HKV * NSPLIT * GG * DH];    // flash partial acc
__device__ float g_pml [BB * HKV * NSPLIT * GG * 2];     // flash partial (m,l)

// ---------------- packed fp32x2 helpers (FFMA2 path, sm_100+) ----------------
__device__ __forceinline__ unsigned long long pk2(float lo, float hi) {
    unsigned long long r;
    asm("mov.b64 %0, {%1,%2};" : "=l"(r) : "f"(lo), "f"(hi));
    return r;
}
__device__ __forceinline__ void upk2(unsigned long long v, float& lo, float& hi) {
    asm("mov.b64 {%0,%1}, %2;" : "=f"(lo), "=f"(hi) : "l"(v));
}
__device__ __forceinline__ void fma2(unsigned long long& d, unsigned long long a, unsigned long long b) {
    asm("fma.rn.f32x2 %0, %1, %2, %0;" : "+l"(d) : "l"(a), "l"(b));
}

// ---------------- projection GEMV body ----------------
// out[b][e] = sum_d x[b][d] * w[d][e].  512 threads, 1 column per thread,
// 32 batch rows as 16 fp32x2 pairs (acc = 32 regs). Coalesced x gather.
__device__ __forceinline__ void proj_body(
    const float* __restrict__ x, const float* __restrict__ w,
    int Ew, int le0, int gcol0, int d0,
    float* __restrict__ part, int partE)
{
    __shared__ float xs[DSPL * XSTR];   // [d_local][b] padded
    const int tid = threadIdx.x;

    // coalesced gather: thread reads float4 rows of x, transposes into smem
    {
        int bb = tid >> 4, lo = tid & 15;
        #pragma unroll
        for (int it = 0; it < 2; it++) {
            int d = lo * 4 + it * 64;
            float4 xv = *(const float4*)(x + (size_t)bb * DD + d0 + d);
            xs[(d + 0) * XSTR + bb] = xv.x;
            xs[(d + 1) * XSTR + bb] = xv.y;
            xs[(d + 2) * XSTR + bb] = xv.z;
            xs[(d + 3) * XSTR + bb] = xv.w;
        }
    }
    __syncthreads();

    const unsigned long long* xs2 = (const unsigned long long*)xs; // row stride XSTR/2

    unsigned long long acc[16];
    #pragma unroll
    for (int jp = 0; jp < 16; jp++) acc[jp] = 0ull;

    const float* wp = w + (size_t)d0 * Ew + le0 + tid;

    for (int blk = 0; blk < DSPL / 4; blk++) {
        float w4[4];
        #pragma unroll
        for (int u = 0; u < 4; u++) w4[u] = wp[(size_t)u * Ew];
        #pragma unroll
        for (int u = 0; u < 4; u++) {
            int dl = blk * 4 + u;
            unsigned long long uw = pk2(w4[u], w4[u]);
            const unsigned long long* xr = xs2 + dl * (XSTR / 2);
            #pragma unroll
            for (int jp = 0; jp < 16; jp++)
                fma2(acc[jp], uw, xr[jp]);
        }
        wp += (size_t)4 * Ew;
    }

    const int split = blockIdx.y;
    float* pb = part + (size_t)split * BB * partE + gcol0 + tid;
    #pragma unroll
    for (int jp = 0; jp < 16; jp++) {
        float lo, hi;
        upk2(acc[jp], lo, hi);
        pb[(size_t)(2 * jp) * partE] = lo;
        pb[(size_t)(2 * jp + 1) * partE] = hi;
    }
}

__global__ void __launch_bounds__(512)
proj_qkv_kernel(const float* __restrict__ x, const float* __restrict__ wq,
                const float* __restrict__ wk, const float* __restrict__ wv)
{
    int e0 = blockIdx.x * 512;
    const float* w; int Ew, le0;
    if (e0 < 4096)      { w = wq; Ew = 4096; le0 = e0; }
    else if (e0 < 5120) { w = wk; Ew = 1024; le0 = e0 - 4096; }
    else                { w = wv; Ew = 1024; le0 = e0 - 5120; }
    proj_body(x, w, Ew, le0, e0, blockIdx.y * DSPL, g_P1, EQKV);
}

__global__ void __launch_bounds__(512)
proj_o_kernel(const float* __restrict__ wo)
{
    int e0 = blockIdx.x * 512;
    proj_body(g_attn, wo, DD, e0, e0, blockIdx.y * DSPL, g_P2, DD);
}

// ---------------- reductions over K-splits ----------------
__global__ void reduce_qkv_kernel()
{
    int idx = blockIdx.x * 256 + threadIdx.x;
    if (idx >= BB * EQKV) return;
    int b = idx / EQKV, col = idx % EQKV;
    float s = 0.f;
    #pragma unroll 8
    for (int sp = 0; sp < SPLITS; sp++)
        s += g_P1[((size_t)sp * BB + b) * EQKV + col];
    if (col < 4096)      g_xq[b * 4096 + col] = s;
    else if (col < 5120) g_xk[b * 1024 + (col - 4096)] = s;
    else                 g_v [b * 1024 + (col - 5120)] = s;
}

__global__ void reduce_o_kernel(float* __restrict__ out)
{
    int idx = blockIdx.x * 256 + threadIdx.x;
    if (idx >= BB * DD) return;
    int b = idx >> 12, col = idx & 4095;
    float s = 0.f;
    #pragma unroll 8
    for (int sp = 0; sp < SPLITS; sp++)
        s += g_P2[((size_t)sp * BB + b) * DD + col];
    out[b * DD + col] = s;
}

// ---------------- RoPE ----------------
__global__ void rotate_kernel(const float* __restrict__ rot, int rot_b_stride)
{
    int hh = blockIdx.x, b = blockIdx.y, tid = threadIdx.x;
    __shared__ float xs[DH];
    const float* src; float* dst;
    if (hh < HH) { src = g_xq + (b * HH + hh) * DH; dst = g_q + (b * HH + hh) * DH; }
    else         { src = g_xk + (b * HKV + (hh - HH)) * DH; dst = g_k + (b * HKV + (hh - HH)) * DH; }
    xs[tid] = src[tid];
    __syncthreads();
    const float* R = rot + (size_t)b * rot_b_stride;
    float a = 0.f;
    #pragma unroll 8
    for (int d = 0; d < DH; d++) a += xs[d] * R[d * DH + tid];
    dst[tid] = a;
}

// ---------------- flash decode: direct-LDG, 256 tokens/CTA, single-pass softmax ----------------
// grid (NSPLIT, HKV, BB), block 256 (8 warps x 32 tokens).
__global__ void __launch_bounds__(256)
attn_kernel(const float* __restrict__ kc, const float* __restrict__ vc,
            const int* __restrict__ sp_ptr)
{
    __shared__ float s_q  [GG * DH];       // scaled q, [g][d]
    __shared__ float s_sc [TCH * GG];      // scores -> probs, [token][g] (float4)
    __shared__ float s_wm [8 * GG];        // per-warp max
    __shared__ float s_sl [8 * GG];        // per-warp exp-sums
    __shared__ float s_MM [GG];            // block max
    __shared__ float s_out[8 * GG * DH];   // per-warp value partials

    const int chunk = blockIdx.x, kvh = blockIdx.y, b = blockIdx.z;
    const int sp = *sp_ptr;
    const int t0 = chunk * TCH;
    if (t0 > sp) return;

    const int tid = threadIdx.x;
    const int wid = tid >> 5, lane = tid & 31;
    const int bkv = b * HKV + kvh;

    const float* kbase = kc + (size_t)bkv * TT * DH;
    const float* vbase = vc + (size_t)bkv * TT * DH;
    const float* gk = g_k + (size_t)bkv * DH;
    const float* gv = g_v + (size_t)bkv * DH;

    // stage scaled q
    if (tid < 128) {
        int g = tid >> 5, c = tid & 31;
        const float sc = 0.08838834764831845f;   // 1/sqrt(128)
        float4 qv = *(const float4*)(g_q + (size_t)(b * HH + kvh * GG + g) * DH + c * 4);
        ((float4*)s_q)[g * 32 + c] = make_float4(qv.x * sc, qv.y * sc, qv.z * sc, qv.w * sc);
    }
    __syncthreads();

    // ---------------- score phase ----------------
    // warp w owns tokens [w*32, w*32+32); 16 lanes per token; lane dims: dg*4 and dg*4+64
    const int tokg = lane >> 4, dg = lane & 15;
    const int jb = wid * 32;

    float4 qr0[GG], qr1[GG];
    #pragma unroll
    for (int g = 0; g < GG; g++) {
        qr0[g] = *(const float4*)(s_q + g * DH + dg * 4);
        qr1[g] = *(const float4*)(s_q + g * DH + dg * 4 + 64);
    }

    float wm0 = -1e30f, wm1 = -1e30f, wm2 = -1e30f, wm3 = -1e30f;
    #pragma unroll 4
    for (int it = 0; it < 16; it++) {
        int jl = jb + it * 2 + tokg;
        int t = t0 + jl;
        const float* kp = (t == sp) ? gk : (kbase + (size_t)t * DH);
        float4 ka = *(const float4*)(kp + dg * 4);
        float4 kb = *(const float4*)(kp + dg * 4 + 64);
        float s0 = ka.x*qr0[0].x + ka.y*qr0[0].y + ka.z*qr0[0].z + ka.w*qr0[0].w
                 + kb.x*qr1[0].x + kb.y*qr1[0].y + kb.z*qr1[0].z + kb.w*qr1[0].w;
        float s1 = ka.x*qr0[1].x + ka.y*qr0[1].y + ka.z*qr0[1].z + ka.w*qr0[1].w
                 + kb.x*qr1[1].x + kb.y*qr1[1].y + kb.z*qr1[1].z + kb.w*qr1[1].w;
        float s2 = ka.x*qr0[2].x + ka.y*qr0[2].y + ka.z*qr0[2].z + ka.w*qr0[2].w
                 + kb.x*qr1[2].x + kb.y*qr1[2].y + kb.z*qr1[2].z + kb.w*qr1[2].w;
        float s3 = ka.x*qr0[3].x + ka.y*qr0[3].y + ka.z*qr0[3].z + ka.w*qr0[3].w
                 + kb.x*qr1[3].x + kb.y*qr1[3].y + kb.z*qr1[3].z + kb.w*qr1[3].w;
        #pragma unroll
        for (int off = 1; off <= 8; off <<= 1) {
            s0 += __shfl_xor_sync(0xffffffffu, s0, off);
            s1 += __shfl_xor_sync(0xffffffffu, s1, off);
            s2 += __shfl_xor_sync(0xffffffffu, s2, off);
            s3 += __shfl_xor_sync(0xffffffffu, s3, off);
        }
        if (t > sp) { s0 = s1 = s2 = s3 = -1e30f; }
        if (dg == 0)
            ((float4*)s_sc)[jl] = make_float4(s0, s1, s2, s3);
        wm0 = fmaxf(wm0, s0); wm1 = fmaxf(wm1, s1);
        wm2 = fmaxf(wm2, s2); wm3 = fmaxf(wm3, s3);
    }
    // merge the two token groups
    wm0 = fmaxf(wm0, __shfl_xor_sync(0xffffffffu, wm0, 16));
    wm1 = fmaxf(wm1, __shfl_xor_sync(0xffffffffu, wm1, 16));
    wm2 = fmaxf(wm2, __shfl_xor_sync(0xffffffffu, wm2, 16));
    wm3 = fmaxf(wm3, __shfl_xor_sync(0xffffffffu, wm3, 16));
    if (lane == 0) {
        s_wm[wid * 4 + 0] = wm0; s_wm[wid * 4 + 1] = wm1;
        s_wm[wid * 4 + 2] = wm2; s_wm[wid * 4 + 3] = wm3;
    }
    __syncthreads();

    // block max per head
    if (tid < 4) {
        float m = s_wm[tid];
        #pragma unroll
        for (int w = 1; w < 8; w++) m = fmaxf(m, s_wm[w * 4 + tid]);
        s_MM[tid] = m;
    }
    __syncthreads();

    // exp + per-warp sums (thread = token)
    {
        float4 sv = ((float4*)s_sc)[tid];
        float p0 = __expf(sv.x - s_MM[0]);
        float p1 = __expf(sv.y - s_MM[1]);
        float p2 = __expf(sv.z - s_MM[2]);
        float p3 = __expf(sv.w - s_MM[3]);
        ((float4*)s_sc)[tid] = make_float4(p0, p1, p2, p3);
        #pragma unroll
        for (int off = 1; off <= 16; off <<= 1) {
            p0 += __shfl_xor_sync(0xffffffffu, p0, off);
            p1 += __shfl_xor_sync(0xffffffffu, p1, off);
            p2 += __shfl_xor_sync(0xffffffffu, p2, off);
            p3 += __shfl_xor_sync(0xffffffffu, p3, off);
        }
        if (lane == 0) {
            s_sl[wid * 4 + 0] = p0; s_sl[wid * 4 + 1] = p1;
            s_sl[wid * 4 + 2] = p2; s_sl[wid * 4 + 3] = p3;
        }
    }
    __syncthreads();

    if (tid < 4) {
        float L = 0.f;
        #pragma unroll
        for (int w = 0; w < 8; w++) L += s_sl[w * 4 + tid];
        size_t mlb = (((size_t)bkv * NSPLIT + chunk) * GG + tid) * 2;
        g_pml[mlb] = s_MM[tid];
        g_pml[mlb + 1] = L;
    }

    // ---------------- value phase ----------------
    // warp w: its 32 tokens; lane owns dims lane*4..+3
    float4 a0 = {0,0,0,0}, a1 = {0,0,0,0}, a2 = {0,0,0,0}, a3 = {0,0,0,0};
    #pragma unroll 4
    for (int j = 0; j < 32; j++) {
        int t = t0 + jb + j;
        const float* vp = (t == sp) ? gv : (vbase + (size_t)t * DH);
        float4 vv = *(const float4*)(vp + lane * 4);
        float4 p4 = ((float4*)s_sc)[jb + j];
        a0.x += p4.x*vv.x; a0.y += p4.x*vv.y; a0.z += p4.x*vv.z; a0.w += p4.x*vv.w;
        a1.x += p4.y*vv.x; a1.y += p4.y*vv.y; a1.z += p4.y*vv.z; a1.w += p4.y*vv.w;
        a2.x += p4.z*vv.x; a2.y += p4.z*vv.y; a2.z += p4.z*vv.z; a2.w += p4.z*vv.w;
        a3.x += p4.w*vv.x; a3.y += p4.w*vv.y; a3.z += p4.w*vv.z; a3.w += p4.w*vv.w;
    }
    {
        float* ob = s_out + wid * (GG * DH);
        *(float4*)(ob + 0 * DH + lane * 4) = a0;
        *(float4*)(ob + 1 * DH + lane * 4) = a1;
        *(float4*)(ob + 2 * DH + lane * 4) = a2;
        *(float4*)(ob + 3 * DH + lane * 4) = a3;
    }
    __syncthreads();

    // cross-warp reduce + write partials
    size_t obase = (((size_t)bkv * NSPLIT + chunk) * GG) * DH;
    #pragma unroll
    for (int r = tid; r < GG * DH; r += 256) {
        float s = 0.f;
        #pragma unroll
        for (int w = 0; w < 8; w++) s += s_out[w * (GG * DH) + r];
        g_pacc[obase + r] = s;
    }
}

// ---------------- combine split-KV partials ----------------
__global__ void combine_kernel(const int* __restrict__ sp_ptr)
{
    const int h = blockIdx.x, b = blockIdx.y, d = threadIdx.x;
    const int sp = *sp_ptr;
    const int nact = sp / TCH + 1;
    const int kvh = h >> 2, g = h & 3;
    const int bkv = b * HKV + kvh;

    float M = -1e30f;
    for (int c = 0; c < nact; c++)
        M = fmaxf(M, g_pml[(((size_t)bkv * NSPLIT + c) * GG + g) * 2]);

    float L = 0.f, acc = 0.f;
    for (int c = 0; c < nact; c++) {
        size_t mlb = (((size_t)bkv * NSPLIT + c) * GG + g) * 2;
        float f = __expf(g_pml[mlb] - M);
        L += g_pml[mlb + 1] * f;
        acc += g_pacc[(((size_t)bkv * NSPLIT + c) * GG + g) * DH + d] * f;
    }
    g_attn[(size_t)(b * HH + h) * DH + d] = acc / L;
}

// ---------------- launcher ----------------
extern "C" void kernel_launch(void* const* d_in, const int* in_sizes, int n_in,
                              void* d_out, int out_size)
{
    const float* x   = (const float*)d_in[0];
    const float* wq  = (const float*)d_in[1];
    const float* wk  = (const float*)d_in[2];
    const float* wv  = (const float*)d_in[3];
    const float* wo  = (const float*)d_in[4];
    const float* rot = (const float*)d_in[5];
    // d_in[6] = attn_mask: not read (semantics derived from start_pos)
    const float* kc  = (const float*)d_in[7];
    const float* vc  = (const float*)d_in[8];
    const int*   sp  = (const int*)d_in[9];
    float* out = (float*)d_out;

    int rot_b_stride = (in_sizes[5] >= BB * DH * DH) ? DH * DH : 0;

    proj_qkv_kernel<<<dim3(EQKV / 512, SPLITS), 512>>>(x, wq, wk, wv);
    reduce_qkv_kernel<<<(BB * EQKV + 255) / 256, 256>>>();
    rotate_kernel<<<dim3(HH + HKV, BB), DH>>>(rot, rot_b_stride);
    attn_kernel<<<dim3(NSPLIT, HKV, BB), 256>>>(kc, vc, sp);
    combine_kernel<<<dim3(HH, BB), DH>>>(sp);
    proj_o_kernel<<<dim3(DD / 512, SPLITS), 512>>>(wo);
    reduce_o_kernel<<<(BB * DD + 255) / 256, 256>>>(out);
}

// round 7
// speedup vs baseline: 2.1600x; 1.1645x over previous
#include <cuda_runtime.h>
#include <cuda_bf16.h>
#include <cstdint>

// Problem constants
#define BB   32      // batch
#define DD   4096    // model dim
#define HH   32      // q heads
#define HKV  8       // kv heads
#define GG   4       // q heads per kv head
#define DH   128     // head dim
#define TT   4096    // cache length
#define EQKV 6144    // 4096 + 1024 + 1024
#define SPLITS 32    // K-splits for projections
#define DSPL 128     // d per split (4096/32)
#define XSTR 36      // padded smem stride (floats) for x tile: 144B, 16B-aligned

// attention split config
#define TCH    256   // tokens per CTA
#define NSPLIT 16    // TT / TCH

// ---------------- scratch (device globals; no runtime allocation) ----------------
__device__ float g_xq[BB * HH * DH];
__device__ float g_xk[BB * HKV * DH];
__device__ float g_v [BB * HKV * DH];
__device__ float g_q [BB * HH * DH];
__device__ float g_k [BB * HKV * DH];
__device__ float g_attn[BB * HH * DH];
__device__ float g_P1[SPLITS * BB * EQKV];               // qkv partials
__device__ float g_P2[SPLITS * BB * DD];                 // wo partials
__device__ float g_pacc[BB * HKV * NSPLIT * GG * DH];    // flash partial acc
__device__ float g_pml [BB * HKV * NSPLIT * GG * 2];     // flash partial (m,l)

// ---------------- packed fp32x2 helpers (FFMA2 path, sm_100+) ----------------
__device__ __forceinline__ unsigned long long pk2(float lo, float hi) {
    unsigned long long r;
    asm("mov.b64 %0, {%1,%2};" : "=l"(r) : "f"(lo), "f"(hi));
    return r;
}
__device__ __forceinline__ void upk2(unsigned long long v, float& lo, float& hi) {
    asm("mov.b64 {%0,%1}, %2;" : "=f"(lo), "=f"(hi) : "l"(v));
}
__device__ __forceinline__ void fma2(unsigned long long& d, unsigned long long a, unsigned long long b) {
    asm("fma.rn.f32x2 %0, %1, %2, %0;" : "+l"(d) : "l"(a), "l"(b));
}

// ---------------- projection GEMV body ----------------
// out[b][e] = sum_d x[b][d] * w[d][e].  256 threads, 1 column per thread,
// 32 batch rows as 16 fp32x2 pairs (acc = 32 regs). LDS.128 x reads (2 pairs/load).
__device__ __forceinline__ void proj_body(
    const float* __restrict__ x, const float* __restrict__ w,
    int Ew, int le0, int gcol0, int d0,
    float* __restrict__ part, int partE)
{
    __shared__ float xs[DSPL * XSTR];   // [d_local][b] padded, rows 16B-aligned
    const int tid = threadIdx.x;

    // coalesced gather: thread reads float4 rows of x, transposes into smem
    {
        int bb = tid >> 3, lo = tid & 7;
        #pragma unroll
        for (int it = 0; it < 4; it++) {
            int d = lo * 4 + it * 32;
            float4 xv = *(const float4*)(x + (size_t)bb * DD + d0 + d);
            xs[(d + 0) * XSTR + bb] = xv.x;
            xs[(d + 1) * XSTR + bb] = xv.y;
            xs[(d + 2) * XSTR + bb] = xv.z;
            xs[(d + 3) * XSTR + bb] = xv.w;
        }
    }
    __syncthreads();

    unsigned long long acc[16];
    #pragma unroll
    for (int jp = 0; jp < 16; jp++) acc[jp] = 0ull;

    const float* wp = w + (size_t)d0 * Ew + le0 + tid;

    for (int blk = 0; blk < DSPL / 4; blk++) {
        float w4[4];
        #pragma unroll
        for (int u = 0; u < 4; u++) w4[u] = wp[(size_t)u * Ew];
        #pragma unroll
        for (int u = 0; u < 4; u++) {
            int dl = blk * 4 + u;
            unsigned long long uw = pk2(w4[u], w4[u]);
            const ulonglong2* xr = (const ulonglong2*)(xs + dl * XSTR);
            #pragma unroll
            for (int jq = 0; jq < 8; jq++) {
                ulonglong2 xv = xr[jq];                 // LDS.128 broadcast: 2 b-pairs
                fma2(acc[2 * jq], uw, xv.x);
                fma2(acc[2 * jq + 1], uw, xv.y);
            }
        }
        wp += (size_t)4 * Ew;
    }

    const int split = blockIdx.y;
    float* pb = part + (size_t)split * BB * partE + gcol0 + tid;
    #pragma unroll
    for (int jp = 0; jp < 16; jp++) {
        float lo, hi;
        upk2(acc[jp], lo, hi);
        pb[(size_t)(2 * jp) * partE] = lo;
        pb[(size_t)(2 * jp + 1) * partE] = hi;
    }
}

__global__ void __launch_bounds__(256)
proj_qkv_kernel(const float* __restrict__ x, const float* __restrict__ wq,
                const float* __restrict__ wk, const float* __restrict__ wv)
{
    int e0 = blockIdx.x * 256;
    const float* w; int Ew, le0;
    if (e0 < 4096)      { w = wq; Ew = 4096; le0 = e0; }
    else if (e0 < 5120) { w = wk; Ew = 1024; le0 = e0 - 4096; }
    else                { w = wv; Ew = 1024; le0 = e0 - 5120; }
    proj_body(x, w, Ew, le0, e0, blockIdx.y * DSPL, g_P1, EQKV);
}

__global__ void __launch_bounds__(256)
proj_o_kernel(const float* __restrict__ wo)
{
    int e0 = blockIdx.x * 256;
    proj_body(g_attn, wo, DD, e0, e0, blockIdx.y * DSPL, g_P2, DD);
}

// ---------------- reductions over K-splits ----------------
__global__ void reduce_qkv_kernel()
{
    int idx = blockIdx.x * 256 + threadIdx.x;
    if (idx >= BB * EQKV) return;
    int b = idx / EQKV, col = idx % EQKV;
    float s = 0.f;
    #pragma unroll 8
    for (int sp = 0; sp < SPLITS; sp++)
        s += g_P1[((size_t)sp * BB + b) * EQKV + col];
    if (col < 4096)      g_xq[b * 4096 + col] = s;
    else if (col < 5120) g_xk[b * 1024 + (col - 4096)] = s;
    else                 g_v [b * 1024 + (col - 5120)] = s;
}

__global__ void reduce_o_kernel(float* __restrict__ out)
{
    int idx = blockIdx.x * 256 + threadIdx.x;
    if (idx >= BB * DD) return;
    int b = idx >> 12, col = idx & 4095;
    float s = 0.f;
    #pragma unroll 8
    for (int sp = 0; sp < SPLITS; sp++)
        s += g_P2[((size_t)sp * BB + b) * DD + col];
    out[b * DD + col] = s;
}

// ---------------- RoPE ----------------
__global__ void rotate_kernel(const float* __restrict__ rot, int rot_b_stride)
{
    int hh = blockIdx.x, b = blockIdx.y, tid = threadIdx.x;
    __shared__ float xs[DH];
    const float* src; float* dst;
    if (hh < HH) { src = g_xq + (b * HH + hh) * DH; dst = g_q + (b * HH + hh) * DH; }
    else         { src = g_xk + (b * HKV + (hh - HH)) * DH; dst = g_k + (b * HKV + (hh - HH)) * DH; }
    xs[tid] = src[tid];
    __syncthreads();
    const float* R = rot + (size_t)b * rot_b_stride;
    float a = 0.f;
    #pragma unroll 8
    for (int d = 0; d < DH; d++) a += xs[d] * R[d * DH + tid];
    dst[tid] = a;
}

// ---------------- flash decode: direct-LDG, 256 tokens/CTA, single-pass softmax ----------------
// grid (NSPLIT, HKV, BB), block 256 (8 warps x 32 tokens).
__global__ void __launch_bounds__(256, 3)
attn_kernel(const float* __restrict__ kc, const float* __restrict__ vc,
            const int* __restrict__ sp_ptr)
{
    __shared__ float s_q  [GG * DH];       // scaled q, [g][d]
    __shared__ float s_sc [TCH * GG];      // scores -> probs, [token][g] (float4)
    __shared__ float s_wm [8 * GG];        // per-warp max
    __shared__ float s_sl [8 * GG];        // per-warp exp-sums
    __shared__ float s_MM [GG];            // block max
    __shared__ float s_out[8 * GG * DH];   // per-warp value partials

    const int chunk = blockIdx.x, kvh = blockIdx.y, b = blockIdx.z;
    const int sp = *sp_ptr;
    const int t0 = chunk * TCH;
    if (t0 > sp) return;

    const int tid = threadIdx.x;
    const int wid = tid >> 5, lane = tid & 31;
    const int bkv = b * HKV + kvh;

    const float* kbase = kc + (size_t)bkv * TT * DH;
    const float* vbase = vc + (size_t)bkv * TT * DH;
    const float* gk = g_k + (size_t)bkv * DH;
    const float* gv = g_v + (size_t)bkv * DH;

    // stage scaled q
    if (tid < 128) {
        int g = tid >> 5, c = tid & 31;
        const float sc = 0.08838834764831845f;   // 1/sqrt(128)
        float4 qv = *(const float4*)(g_q + (size_t)(b * HH + kvh * GG + g) * DH + c * 4);
        ((float4*)s_q)[g * 32 + c] = make_float4(qv.x * sc, qv.y * sc, qv.z * sc, qv.w * sc);
    }
    __syncthreads();

    // ---------------- score phase ----------------
    // warp w owns tokens [w*32, w*32+32); 16 lanes per token; lane dims: dg*4 and dg*4+64
    const int tokg = lane >> 4, dg = lane & 15;
    const int jb = wid * 32;

    float4 qr0[GG], qr1[GG];
    #pragma unroll
    for (int g = 0; g < GG; g++) {
        qr0[g] = *(const float4*)(s_q + g * DH + dg * 4);
        qr1[g] = *(const float4*)(s_q + g * DH + dg * 4 + 64);
    }

    float wm0 = -1e30f, wm1 = -1e30f, wm2 = -1e30f, wm3 = -1e30f;
    // prefetched K registers
    float4 ka, kb;
    {
        int t = t0 + jb + tokg;
        const float* kp = (t == sp) ? gk : (kbase + (size_t)t * DH);
        ka = *(const float4*)(kp + dg * 4);
        kb = *(const float4*)(kp + dg * 4 + 64);
    }
    #pragma unroll
    for (int it = 0; it < 16; it++) {
        int jl = jb + it * 2 + tokg;
        int t = t0 + jl;
        float4 ca = ka, cb = kb;
        if (it < 15) {
            int tn = t0 + jb + (it + 1) * 2 + tokg;
            const float* kp = (tn == sp) ? gk : (kbase + (size_t)tn * DH);
            ka = *(const float4*)(kp + dg * 4);
            kb = *(const float4*)(kp + dg * 4 + 64);
        }
        float s0 = ca.x*qr0[0].x + ca.y*qr0[0].y + ca.z*qr0[0].z + ca.w*qr0[0].w
                 + cb.x*qr1[0].x + cb.y*qr1[0].y + cb.z*qr1[0].z + cb.w*qr1[0].w;
        float s1 = ca.x*qr0[1].x + ca.y*qr0[1].y + ca.z*qr0[1].z + ca.w*qr0[1].w
                 + cb.x*qr1[1].x + cb.y*qr1[1].y + cb.z*qr1[1].z + cb.w*qr1[1].w;
        float s2 = ca.x*qr0[2].x + ca.y*qr0[2].y + ca.z*qr0[2].z + ca.w*qr0[2].w
                 + cb.x*qr1[2].x + cb.y*qr1[2].y + cb.z*qr1[2].z + cb.w*qr1[2].w;
        float s3 = ca.x*qr0[3].x + ca.y*qr0[3].y + ca.z*qr0[3].z + ca.w*qr0[3].w
                 + cb.x*qr1[3].x + cb.y*qr1[3].y + cb.z*qr1[3].z + cb.w*qr1[3].w;
        #pragma unroll
        for (int off = 1; off <= 8; off <<= 1) {
            s0 += __shfl_xor_sync(0xffffffffu, s0, off);
            s1 += __shfl_xor_sync(0xffffffffu, s1, off);
            s2 += __shfl_xor_sync(0xffffffffu, s2, off);
            s3 += __shfl_xor_sync(0xffffffffu, s3, off);
        }
        if (t > sp) { s0 = s1 = s2 = s3 = -1e30f; }
        if (dg == 0)
            ((float4*)s_sc)[jl] = make_float4(s0, s1, s2, s3);
        wm0 = fmaxf(wm0, s0); wm1 = fmaxf(wm1, s1);
        wm2 = fmaxf(wm2, s2); wm3 = fmaxf(wm3, s3);
    }
    // merge the two token groups
    wm0 = fmaxf(wm0, __shfl_xor_sync(0xffffffffu, wm0, 16));
    wm1 = fmaxf(wm1, __shfl_xor_sync(0xffffffffu, wm1, 16));
    wm2 = fmaxf(wm2, __shfl_xor_sync(0xffffffffu, wm2, 16));
    wm3 = fmaxf(wm3, __shfl_xor_sync(0xffffffffu, wm3, 16));
    if (lane == 0) {
        s_wm[wid * 4 + 0] = wm0; s_wm[wid * 4 + 1] = wm1;
        s_wm[wid * 4 + 2] = wm2; s_wm[wid * 4 + 3] = wm3;
    }
    __syncthreads();

    // block max per head
    if (tid < 4) {
        float m = s_wm[tid];
        #pragma unroll
        for (int w = 1; w < 8; w++) m = fmaxf(m, s_wm[w * 4 + tid]);
        s_MM[tid] = m;
    }
    __syncthreads();

    // exp + per-warp sums (thread = token)
    {
        float4 sv = ((float4*)s_sc)[tid];
        float p0 = __expf(sv.x - s_MM[0]);
        float p1 = __expf(sv.y - s_MM[1]);
        float p2 = __expf(sv.z - s_MM[2]);
        float p3 = __expf(sv.w - s_MM[3]);
        ((float4*)s_sc)[tid] = make_float4(p0, p1, p2, p3);
        #pragma unroll
        for (int off = 1; off <= 16; off <<= 1) {
            p0 += __shfl_xor_sync(0xffffffffu, p0, off);
            p1 += __shfl_xor_sync(0xffffffffu, p1, off);
            p2 += __shfl_xor_sync(0xffffffffu, p2, off);
            p3 += __shfl_xor_sync(0xffffffffu, p3, off);
        }
        if (lane == 0) {
            s_sl[wid * 4 + 0] = p0; s_sl[wid * 4 + 1] = p1;
            s_sl[wid * 4 + 2] = p2; s_sl[wid * 4 + 3] = p3;
        }
    }
    __syncthreads();

    if (tid < 4) {
        float L = 0.f;
        #pragma unroll
        for (int w = 0; w < 8; w++) L += s_sl[w * 4 + tid];
        size_t mlb = (((size_t)bkv * NSPLIT + chunk) * GG + tid) * 2;
        g_pml[mlb] = s_MM[tid];
        g_pml[mlb + 1] = L;
    }

    // ---------------- value phase ----------------
    // warp w: its 32 tokens; lane owns dims lane*4..+3; unrolled x4 for MLP
    float4 a0 = {0,0,0,0}, a1 = {0,0,0,0}, a2 = {0,0,0,0}, a3 = {0,0,0,0};
    #pragma unroll
    for (int jo = 0; jo < 32; jo += 4) {
        float4 vv[4], p4[4];
        #pragma unroll
        for (int u = 0; u < 4; u++) {
            int t = t0 + jb + jo + u;
            const float* vp = (t == sp) ? gv : (vbase + (size_t)t * DH);
            vv[u] = *(const float4*)(vp + lane * 4);
            p4[u] = ((float4*)s_sc)[jb + jo + u];
        }
        #pragma unroll
        for (int u = 0; u < 4; u++) {
            a0.x += p4[u].x*vv[u].x; a0.y += p4[u].x*vv[u].y; a0.z += p4[u].x*vv[u].z; a0.w += p4[u].x*vv[u].w;
            a1.x += p4[u].y*vv[u].x; a1.y += p4[u].y*vv[u].y; a1.z += p4[u].y*vv[u].z; a1.w += p4[u].y*vv[u].w;
            a2.x += p4[u].z*vv[u].x; a2.y += p4[u].z*vv[u].y; a2.z += p4[u].z*vv[u].z; a2.w += p4[u].z*vv[u].w;
            a3.x += p4[u].w*vv[u].x; a3.y += p4[u].w*vv[u].y; a3.z += p4[u].w*vv[u].z; a3.w += p4[u].w*vv[u].w;
        }
    }
    {
        float* ob = s_out + wid * (GG * DH);
        *(float4*)(ob + 0 * DH + lane * 4) = a0;
        *(float4*)(ob + 1 * DH + lane * 4) = a1;
        *(float4*)(ob + 2 * DH + lane * 4) = a2;
        *(float4*)(ob + 3 * DH + lane * 4) = a3;
    }
    __syncthreads();

    // cross-warp reduce + write partials
    size_t obase = (((size_t)bkv * NSPLIT + chunk) * GG) * DH;
    #pragma unroll
    for (int r = tid; r < GG * DH; r += 256) {
        float s = 0.f;
        #pragma unroll
        for (int w = 0; w < 8; w++) s += s_out[w * (GG * DH) + r];
        g_pacc[obase + r] = s;
    }
}

// ---------------- combine split-KV partials ----------------
__global__ void combine_kernel(const int* __restrict__ sp_ptr)
{
    const int h = blockIdx.x, b = blockIdx.y, d = threadIdx.x;
    const int sp = *sp_ptr;
    const int nact = sp / TCH + 1;
    const int kvh = h >> 2, g = h & 3;
    const int bkv = b * HKV + kvh;

    float M = -1e30f;
    for (int c = 0; c < nact; c++)
        M = fmaxf(M, g_pml[(((size_t)bkv * NSPLIT + c) * GG + g) * 2]);

    float L = 0.f, acc = 0.f;
    for (int c = 0; c < nact; c++) {
        size_t mlb = (((size_t)bkv * NSPLIT + c) * GG + g) * 2;
        float f = __expf(g_pml[mlb] - M);
        L += g_pml[mlb + 1] * f;
        acc += g_pacc[(((size_t)bkv * NSPLIT + c) * GG + g) * DH + d] * f;
    }
    g_attn[(size_t)(b * HH + h) * DH + d] = acc / L;
}

// ---------------- launcher ----------------
extern "C" void kernel_launch(void* const* d_in, const int* in_sizes, int n_in,
                              void* d_out, int out_size)
{
    const float* x   = (const float*)d_in[0];
    const float* wq  = (const float*)d_in[1];
    const float* wk  = (const float*)d_in[2];
    const float* wv  = (const float*)d_in[3];
    const float* wo  = (const float*)d_in[4];
    const float* rot = (const float*)d_in[5];
    // d_in[6] = attn_mask: not read (semantics derived from start_pos)
    const float* kc  = (const float*)d_in[7];
    const float* vc  = (const float*)d_in[8];
    const int*   sp  = (const int*)d_in[9];
    float* out = (float*)d_out;

    int rot_b_stride = (in_sizes[5] >= BB * DH * DH) ? DH * DH : 0;

    proj_qkv_kernel<<<dim3(EQKV / 256, SPLITS), 256>>>(x, wq, wk, wv);
    reduce_qkv_kernel<<<(BB * EQKV + 255) / 256, 256>>>();
    rotate_kernel<<<dim3(HH + HKV, BB), DH>>>(rot, rot_b_stride);
    attn_kernel<<<dim3(NSPLIT, HKV, BB), 256>>>(kc, vc, sp);
    combine_kernel<<<dim3(HH, BB), DH>>>(sp);
    proj_o_kernel<<<dim3(DD / 256, SPLITS), 256>>>(wo);
    reduce_o_kernel<<<(BB * DD + 255) / 256, 256>>>(out);
}

// round 8
// speedup vs baseline: 2.3399x; 1.0833x over previous
#include <cuda_runtime.h>
#include <cuda_bf16.h>
#include <cstdint>

// Problem constants
#define BB   32      // batch
#define DD   4096    // model dim
#define HH   32      // q heads
#define HKV  8       // kv heads
#define GG   4       // q heads per kv head
#define DH   128     // head dim
#define TT   4096    // cache length
#define EQKV 6144    // 4096 + 1024 + 1024
#define SPLITS 32    // K-splits for projections
#define DSPL 128     // d per split (4096/32)
#define XSTR 36      // padded smem stride (floats) for x tile: 144B, 16B-aligned

// attention split config
#define TCH    512   // tokens per CTA
#define NSPLIT 8     // TT / TCH

// ---------------- scratch (device globals; no runtime allocation) ----------------
__device__ float g_v [BB * HKV * DH];
__device__ float g_q [BB * HH * DH];
__device__ float g_k [BB * HKV * DH];
__device__ float g_attn[BB * HH * DH];
__device__ float g_P1[SPLITS * BB * EQKV];               // qkv partials
__device__ float g_P2[SPLITS * BB * DD];                 // wo partials
__device__ float g_pacc[BB * HKV * NSPLIT * GG * DH];    // flash partial acc
__device__ float g_pml [BB * HKV * NSPLIT * GG * 2];     // flash partial (m,l)

// ---------------- packed fp32x2 helpers (FFMA2 path, sm_100+) ----------------
__device__ __forceinline__ unsigned long long pk2(float lo, float hi) {
    unsigned long long r;
    asm("mov.b64 %0, {%1,%2};" : "=l"(r) : "f"(lo), "f"(hi));
    return r;
}
__device__ __forceinline__ void upk2(unsigned long long v, float& lo, float& hi) {
    asm("mov.b64 {%0,%1}, %2;" : "=f"(lo), "=f"(hi) : "l"(v));
}
__device__ __forceinline__ void fma2(unsigned long long& d, unsigned long long a, unsigned long long b) {
    asm("fma.rn.f32x2 %0, %1, %2, %0;" : "+l"(d) : "l"(a), "l"(b));
}

// ---------------- projection GEMV body ----------------
// out[b][e] = sum_d x[b][d] * w[d][e].  256 threads.
// Thread = (col-pair c2, batch-half bh): 2 adjacent cols, 16 batches (8 fp32x2 pairs).
// Per d-row: 1 LDG.64 (w) + 4 LDS.128 (x pairs) + 16 FFMA2  -> FFMA-pipe bound.
__device__ __forceinline__ void proj_body(
    const float* __restrict__ x, const float* __restrict__ w,
    int Ew, int le0, int gcol0, int d0,
    float* __restrict__ part, int partE)
{
    __shared__ float xs[DSPL * XSTR];   // [d_local][b] padded, rows 16B-aligned
    const int tid = threadIdx.x;

    // coalesced gather: thread reads float4 rows of x, transposes into smem
    {
        int bb = tid >> 3, lo = tid & 7;
        #pragma unroll
        for (int it = 0; it < 4; it++) {
            int d = lo * 4 + it * 32;
            float4 xv = *(const float4*)(x + (size_t)bb * DD + d0 + d);
            xs[(d + 0) * XSTR + bb] = xv.x;
            xs[(d + 1) * XSTR + bb] = xv.y;
            xs[(d + 2) * XSTR + bb] = xv.z;
            xs[(d + 3) * XSTR + bb] = xv.w;
        }
    }
    __syncthreads();

    const int c2 = tid & 127;     // col pair index (cols c2*2, c2*2+1)
    const int bh = tid >> 7;      // batch half (b 0-15 or 16-31)

    unsigned long long acc[8][2];
    #pragma unroll
    for (int p = 0; p < 8; p++) { acc[p][0] = 0ull; acc[p][1] = 0ull; }

    const float* wp = w + (size_t)d0 * Ew + le0 + c2 * 2;

    for (int blk = 0; blk < DSPL / 4; blk++) {
        float2 wr[4];
        #pragma unroll
        for (int u = 0; u < 4; u++) wr[u] = *(const float2*)(wp + (size_t)u * Ew);
        #pragma unroll
        for (int u = 0; u < 4; u++) {
            int dl = blk * 4 + u;
            unsigned long long wA = pk2(wr[u].x, wr[u].x);
            unsigned long long wB = pk2(wr[u].y, wr[u].y);
            const float* xrow = xs + dl * XSTR + bh * 16;
            #pragma unroll
            for (int jq = 0; jq < 4; jq++) {
                ulonglong2 xv = *(const ulonglong2*)(xrow + jq * 4);  // 4 batches
                fma2(acc[2 * jq + 0][0], wA, xv.x);
                fma2(acc[2 * jq + 0][1], wB, xv.x);
                fma2(acc[2 * jq + 1][0], wA, xv.y);
                fma2(acc[2 * jq + 1][1], wB, xv.y);
            }
        }
        wp += (size_t)4 * Ew;
    }

    const int split = blockIdx.y;
    float* pb = part + (size_t)split * BB * partE + gcol0 + c2 * 2;
    #pragma unroll
    for (int p = 0; p < 8; p++) {
        float loA, hiA, loB, hiB;
        upk2(acc[p][0], loA, hiA);   // col0: batches (bh*16+2p, bh*16+2p+1)
        upk2(acc[p][1], loB, hiB);   // col1
        int b0 = bh * 16 + 2 * p;
        *(float2*)(pb + (size_t)b0 * partE)       = make_float2(loA, loB);
        *(float2*)(pb + (size_t)(b0 + 1) * partE) = make_float2(hiA, hiB);
    }
}

__global__ void __launch_bounds__(256)
proj_qkv_kernel(const float* __restrict__ x, const float* __restrict__ wq,
                const float* __restrict__ wk, const float* __restrict__ wv)
{
    int e0 = blockIdx.x * 256;
    const float* w; int Ew, le0;
    if (e0 < 4096)      { w = wq; Ew = 4096; le0 = e0; }
    else if (e0 < 5120) { w = wk; Ew = 1024; le0 = e0 - 4096; }
    else                { w = wv; Ew = 1024; le0 = e0 - 5120; }
    proj_body(x, w, Ew, le0, e0, blockIdx.y * DSPL, g_P1, EQKV);
}

__global__ void __launch_bounds__(256)
proj_o_kernel(const float* __restrict__ wo)
{
    int e0 = blockIdx.x * 256;
    proj_body(g_attn, wo, DD, e0, e0, blockIdx.y * DSPL, g_P2, DD);
}

// ---------------- fused split-reduce + RoPE ----------------
// grid (48, BB), block 128.  hh<32: q head; 32..39: k head; 40..47: v head (no rotate).
__global__ void __launch_bounds__(128)
fused_reduce_rot_kernel(const float* __restrict__ rot, int rot_b_stride)
{
    const int hh = blockIdx.x, b = blockIdx.y, tid = threadIdx.x;
    int col;
    if (hh < 32)      col = hh * 128 + tid;
    else if (hh < 40) col = 4096 + (hh - 32) * 128 + tid;
    else              col = 5120 + (hh - 40) * 128 + tid;

    const float* p = g_P1 + (size_t)b * EQKV + col;
    float s = 0.f;
    #pragma unroll 8
    for (int sp = 0; sp < SPLITS; sp++)
        s += p[(size_t)sp * BB * EQKV];

    if (hh >= 40) {                      // v: plain reduce
        g_v[(size_t)b * 1024 + (hh - 40) * 128 + tid] = s;
        return;
    }

    __shared__ float xsr[DH];
    xsr[tid] = s;
    __syncthreads();
    const float* R = rot + (size_t)b * rot_b_stride;
    float a = 0.f;
    #pragma unroll 8
    for (int dd = 0; dd < DH; dd++) a += xsr[dd] * R[dd * DH + tid];

    if (hh < 32) g_q[(size_t)(b * HH + hh) * DH + tid] = a;
    else         g_k[(size_t)(b * HKV + (hh - 32)) * DH + tid] = a;
}

// ---------------- reduce wo partials ----------------
__global__ void reduce_o_kernel(float* __restrict__ out)
{
    int idx = blockIdx.x * 256 + threadIdx.x;
    if (idx >= BB * DD) return;
    int b = idx >> 12, col = idx & 4095;
    float s = 0.f;
    #pragma unroll 8
    for (int sp = 0; sp < SPLITS; sp++)
        s += g_P2[((size_t)sp * BB + b) * DD + col];
    out[b * DD + col] = s;
}

// ---------------- flash decode: direct-LDG, 512 tokens/CTA, single-pass softmax ----------------
// grid (NSPLIT, HKV, BB), block 256 (8 warps x 64 tokens).
__global__ void __launch_bounds__(256, 3)
attn_kernel(const float* __restrict__ kc, const float* __restrict__ vc,
            const int* __restrict__ sp_ptr)
{
    __shared__ float s_q  [GG * DH];       // scaled q, [g][d]
    __shared__ float s_sc [TCH * GG];      // scores -> probs, [token][g] (float4)
    __shared__ float s_wm [8 * GG];        // per-warp max
    __shared__ float s_sl [8 * GG];        // per-warp exp-sums
    __shared__ float s_MM [GG];            // block max
    __shared__ float s_out[8 * GG * DH];   // per-warp value partials

    const int chunk = blockIdx.x, kvh = blockIdx.y, b = blockIdx.z;
    const int sp = *sp_ptr;
    const int t0 = chunk * TCH;
    if (t0 > sp) return;

    const int tid = threadIdx.x;
    const int wid = tid >> 5, lane = tid & 31;
    const int bkv = b * HKV + kvh;

    const float* kbase = kc + (size_t)bkv * TT * DH;
    const float* vbase = vc + (size_t)bkv * TT * DH;
    const float* gk = g_k + (size_t)bkv * DH;
    const float* gv = g_v + (size_t)bkv * DH;

    // stage scaled q
    if (tid < 128) {
        int g = tid >> 5, c = tid & 31;
        const float sc = 0.08838834764831845f;   // 1/sqrt(128)
        float4 qv = *(const float4*)(g_q + (size_t)(b * HH + kvh * GG + g) * DH + c * 4);
        ((float4*)s_q)[g * 32 + c] = make_float4(qv.x * sc, qv.y * sc, qv.z * sc, qv.w * sc);
    }
    __syncthreads();

    // ---------------- score phase ----------------
    // warp w owns tokens [w*64, w*64+64); 16 lanes per token; lane dims: dg*4 and dg*4+64
    const int tokg = lane >> 4, dg = lane & 15;
    const int jb = wid * 64;

    float4 qr0[GG], qr1[GG];
    #pragma unroll
    for (int g = 0; g < GG; g++) {
        qr0[g] = *(const float4*)(s_q + g * DH + dg * 4);
        qr1[g] = *(const float4*)(s_q + g * DH + dg * 4 + 64);
    }

    float wm0 = -1e30f, wm1 = -1e30f, wm2 = -1e30f, wm3 = -1e30f;
    // prefetched K registers
    float4 ka, kb;
    {
        int t = t0 + jb + tokg;
        const float* kp = (t == sp) ? gk : (kbase + (size_t)t * DH);
        ka = *(const float4*)(kp + dg * 4);
        kb = *(const float4*)(kp + dg * 4 + 64);
    }
    #pragma unroll 8
    for (int it = 0; it < 32; it++) {
        int jl = jb + it * 2 + tokg;
        int t = t0 + jl;
        float4 ca = ka, cb = kb;
        if (it < 31) {
            int tn = t0 + jb + (it + 1) * 2 + tokg;
            const float* kp = (tn == sp) ? gk : (kbase + (size_t)tn * DH);
            ka = *(const float4*)(kp + dg * 4);
            kb = *(const float4*)(kp + dg * 4 + 64);
        }
        float s0 = ca.x*qr0[0].x + ca.y*qr0[0].y + ca.z*qr0[0].z + ca.w*qr0[0].w
                 + cb.x*qr1[0].x + cb.y*qr1[0].y + cb.z*qr1[0].z + cb.w*qr1[0].w;
        float s1 = ca.x*qr0[1].x + ca.y*qr0[1].y + ca.z*qr0[1].z + ca.w*qr0[1].w
                 + cb.x*qr1[1].x + cb.y*qr1[1].y + cb.z*qr1[1].z + cb.w*qr1[1].w;
        float s2 = ca.x*qr0[2].x + ca.y*qr0[2].y + ca.z*qr0[2].z + ca.w*qr0[2].w
                 + cb.x*qr1[2].x + cb.y*qr1[2].y + cb.z*qr1[2].z + cb.w*qr1[2].w;
        float s3 = ca.x*qr0[3].x + ca.y*qr0[3].y + ca.z*qr0[3].z + ca.w*qr0[3].w
                 + cb.x*qr1[3].x + cb.y*qr1[3].y + cb.z*qr1[3].z + cb.w*qr1[3].w;
        #pragma unroll
        for (int off = 1; off <= 8; off <<= 1) {
            s0 += __shfl_xor_sync(0xffffffffu, s0, off);
            s1 += __shfl_xor_sync(0xffffffffu, s1, off);
            s2 += __shfl_xor_sync(0xffffffffu, s2, off);
            s3 += __shfl_xor_sync(0xffffffffu, s3, off);
        }
        if (t > sp) { s0 = s1 = s2 = s3 = -1e30f; }
        if (dg == 0)
            ((float4*)s_sc)[jl] = make_float4(s0, s1, s2, s3);
        wm0 = fmaxf(wm0, s0); wm1 = fmaxf(wm1, s1);
        wm2 = fmaxf(wm2, s2); wm3 = fmaxf(wm3, s3);
    }
    // merge the two token groups
    wm0 = fmaxf(wm0, __shfl_xor_sync(0xffffffffu, wm0, 16));
    wm1 = fmaxf(wm1, __shfl_xor_sync(0xffffffffu, wm1, 16));
    wm2 = fmaxf(wm2, __shfl_xor_sync(0xffffffffu, wm2, 16));
    wm3 = fmaxf(wm3, __shfl_xor_sync(0xffffffffu, wm3, 16));
    if (lane == 0) {
        s_wm[wid * 4 + 0] = wm0; s_wm[wid * 4 + 1] = wm1;
        s_wm[wid * 4 + 2] = wm2; s_wm[wid * 4 + 3] = wm3;
    }
    __syncthreads();

    // block max per head
    if (tid < 4) {
        float m = s_wm[tid];
        #pragma unroll
        for (int w = 1; w < 8; w++) m = fmaxf(m, s_wm[w * 4 + tid]);
        s_MM[tid] = m;
    }
    __syncthreads();

    // exp + per-warp sums (thread = 2 tokens)
    {
        float4 sva = ((float4*)s_sc)[tid];
        float4 svb = ((float4*)s_sc)[tid + 256];
        float m0 = s_MM[0], m1 = s_MM[1], m2 = s_MM[2], m3 = s_MM[3];
        float pa0 = __expf(sva.x - m0), pb0 = __expf(svb.x - m0);
        float pa1 = __expf(sva.y - m1), pb1 = __expf(svb.y - m1);
        float pa2 = __expf(sva.z - m2), pb2 = __expf(svb.z - m2);
        float pa3 = __expf(sva.w - m3), pb3 = __expf(svb.w - m3);
        ((float4*)s_sc)[tid]       = make_float4(pa0, pa1, pa2, pa3);
        ((float4*)s_sc)[tid + 256] = make_float4(pb0, pb1, pb2, pb3);
        float p0 = pa0 + pb0, p1 = pa1 + pb1, p2 = pa2 + pb2, p3 = pa3 + pb3;
        #pragma unroll
        for (int off = 1; off <= 16; off <<= 1) {
            p0 += __shfl_xor_sync(0xffffffffu, p0, off);
            p1 += __shfl_xor_sync(0xffffffffu, p1, off);
            p2 += __shfl_xor_sync(0xffffffffu, p2, off);
            p3 += __shfl_xor_sync(0xffffffffu, p3, off);
        }
        if (lane == 0) {
            s_sl[wid * 4 + 0] = p0; s_sl[wid * 4 + 1] = p1;
            s_sl[wid * 4 + 2] = p2; s_sl[wid * 4 + 3] = p3;
        }
    }
    __syncthreads();

    if (tid < 4) {
        float L = 0.f;
        #pragma unroll
        for (int w = 0; w < 8; w++) L += s_sl[w * 4 + tid];
        size_t mlb = (((size_t)bkv * NSPLIT + chunk) * GG + tid) * 2;
        g_pml[mlb] = s_MM[tid];
        g_pml[mlb + 1] = L;
    }

    // ---------------- value phase ----------------
    // warp w: its 64 tokens; lane owns dims lane*4..+3; unrolled x4 for MLP
    float4 a0 = {0,0,0,0}, a1 = {0,0,0,0}, a2 = {0,0,0,0}, a3 = {0,0,0,0};
    #pragma unroll 4
    for (int jo = 0; jo < 64; jo += 4) {
        float4 vv[4], p4[4];
        #pragma unroll
        for (int u = 0; u < 4; u++) {
            int t = t0 + jb + jo + u;
            const float* vp = (t == sp) ? gv : (vbase + (size_t)t * DH);
            vv[u] = *(const float4*)(vp + lane * 4);
            p4[u] = ((float4*)s_sc)[jb + jo + u];
        }
        #pragma unroll
        for (int u = 0; u < 4; u++) {
            a0.x += p4[u].x*vv[u].x; a0.y += p4[u].x*vv[u].y; a0.z += p4[u].x*vv[u].z; a0.w += p4[u].x*vv[u].w;
            a1.x += p4[u].y*vv[u].x; a1.y += p4[u].y*vv[u].y; a1.z += p4[u].y*vv[u].z; a1.w += p4[u].y*vv[u].w;
            a2.x += p4[u].z*vv[u].x; a2.y += p4[u].z*vv[u].y; a2.z += p4[u].z*vv[u].z; a2.w += p4[u].z*vv[u].w;
            a3.x += p4[u].w*vv[u].x; a3.y += p4[u].w*vv[u].y; a3.z += p4[u].w*vv[u].z; a3.w += p4[u].w*vv[u].w;
        }
    }
    {
        float* ob = s_out + wid * (GG * DH);
        *(float4*)(ob + 0 * DH + lane * 4) = a0;
        *(float4*)(ob + 1 * DH + lane * 4) = a1;
        *(float4*)(ob + 2 * DH + lane * 4) = a2;
        *(float4*)(ob + 3 * DH + lane * 4) = a3;
    }
    __syncthreads();

    // cross-warp reduce + write partials
    size_t obase = (((size_t)bkv * NSPLIT + chunk) * GG) * DH;
    #pragma unroll
    for (int r = tid; r < GG * DH; r += 256) {
        float s = 0.f;
        #pragma unroll
        for (int w = 0; w < 8; w++) s += s_out[w * (GG * DH) + r];
        g_pacc[obase + r] = s;
    }
}

// ---------------- combine split-KV partials ----------------
__global__ void combine_kernel(const int* __restrict__ sp_ptr)
{
    const int h = blockIdx.x, b = blockIdx.y, d = threadIdx.x;
    const int sp = *sp_ptr;
    const int nact = sp / TCH + 1;
    const int kvh = h >> 2, g = h & 3;
    const int bkv = b * HKV + kvh;

    float M = -1e30f;
    for (int c = 0; c < nact; c++)
        M = fmaxf(M, g_pml[(((size_t)bkv * NSPLIT + c) * GG + g) * 2]);

    float L = 0.f, acc = 0.f;
    for (int c = 0; c < nact; c++) {
        size_t mlb = (((size_t)bkv * NSPLIT + c) * GG + g) * 2;
        float f = __expf(g_pml[mlb] - M);
        L += g_pml[mlb + 1] * f;
        acc += g_pacc[(((size_t)bkv * NSPLIT + c) * GG + g) * DH + d] * f;
    }
    g_attn[(size_t)(b * HH + h) * DH + d] = acc / L;
}

// ---------------- launcher ----------------
extern "C" void kernel_launch(void* const* d_in, const int* in_sizes, int n_in,
                              void* d_out, int out_size)
{
    const float* x   = (const float*)d_in[0];
    const float* wq  = (const float*)d_in[1];
    const float* wk  = (const float*)d_in[2];
    const float* wv  = (const float*)d_in[3];
    const float* wo  = (const float*)d_in[4];
    const float* rot = (const float*)d_in[5];
    // d_in[6] = attn_mask: not read (semantics derived from start_pos)
    const float* kc  = (const float*)d_in[7];
    const float* vc  = (const float*)d_in[8];
    const int*   sp  = (const int*)d_in[9];
    float* out = (float*)d_out;

    int rot_b_stride = (in_sizes[5] >= BB * DH * DH) ? DH * DH : 0;

    proj_qkv_kernel<<<dim3(EQKV / 256, SPLITS), 256>>>(x, wq, wk, wv);
    fused_reduce_rot_kernel<<<dim3(48, BB), 128>>>(rot, rot_b_stride);
    attn_kernel<<<dim3(NSPLIT, HKV, BB), 256>>>(kc, vc, sp);
    combine_kernel<<<dim3(HH, BB), DH>>>(sp);
    proj_o_kernel<<<dim3(DD / 256, SPLITS), 256>>>(wo);
    reduce_o_kernel<<<(BB * DD + 255) / 256, 256>>>(out);
}